// round 3
// baseline (speedup 1.0000x reference)
#include <cuda_runtime.h>

// TransducerJoint: h[b,t,u,:] = f[b,t,:] + g[b,u,:] if t < f_len[b] && u < g_len[b] else 0
// B=16, T=256, U=96, H=512 (fp32). Output 805 MB -> pure HBM-write-bound.
// R3: 256-bit streaming stores (st.global.cs.v8.f32, sm_103a) to halve L1tex
//     store wavefronts. 64 h8-lanes x 2 u-lanes per block, 4 u iters/thread.

#define B_ 16
#define T_ 256
#define U_ 96
#define H_ 512
#define H8_ (H_ / 8)      // 64 float8 slices per H-row
#define U_PER_BLK 8

__device__ __forceinline__ void st_cs_v8(float* p, const float4 a, const float4 b)
{
    asm volatile(
        "st.global.cs.v8.f32 [%0], {%1,%2,%3,%4,%5,%6,%7,%8};"
        :: "l"(p),
           "f"(a.x), "f"(a.y), "f"(a.z), "f"(a.w),
           "f"(b.x), "f"(b.y), "f"(b.z), "f"(b.w)
        : "memory");
}

__global__ __launch_bounds__(128) void transducer_joint_kernel(
    const float4* __restrict__ f,      // (B, T, H/4)
    const float4* __restrict__ g,      // (B, U, H/4)
    const int*    __restrict__ f_len,  // (B,)
    const int*    __restrict__ g_len,  // (B,)
    float*        __restrict__ out)    // (B, T, U, H)
{
    const int h8    = threadIdx.x & 63;        // 0..63  (which 32B slice of H)
    const int ulane = threadIdx.x >> 6;        // 0..1
    const int u0    = blockIdx.x * U_PER_BLK;
    const int t     = blockIdx.y;
    const int b     = blockIdx.z;

    const bool t_ok = t < f_len[b];
    const int  gl   = g_len[b];

    // f slice: two float4 = 32 bytes, loaded once, reused for 4 u's
    const float4* frow = f + ((size_t)b * T_ + t) * (H_ / 4) + h8 * 2;
    const float4 fa = frow[0];
    const float4 fb = frow[1];

    const float4 zero = make_float4(0.f, 0.f, 0.f, 0.f);

    const float4* gbase = g + ((size_t)b * U_ + u0) * (H_ / 4) + h8 * 2;
    float* obase = out + (((size_t)b * T_ + t) * U_ + u0) * H_ + h8 * 8;

#pragma unroll
    for (int i = 0; i < U_PER_BLK / 2; ++i) {
        const int du = ulane + 2 * i;
        const int u  = u0 + du;
        float4 ra = zero, rb = zero;
        if (t_ok && u < gl) {
            const float4 ga = __ldg(gbase + (size_t)du * (H_ / 4));
            const float4 gb = __ldg(gbase + (size_t)du * (H_ / 4) + 1);
            ra.x = fa.x + ga.x;  ra.y = fa.y + ga.y;
            ra.z = fa.z + ga.z;  ra.w = fa.w + ga.w;
            rb.x = fb.x + gb.x;  rb.y = fb.y + gb.y;
            rb.z = fb.z + gb.z;  rb.w = fb.w + gb.w;
        }
        st_cs_v8(obase + (size_t)du * H_, ra, rb);
    }
}

extern "C" void kernel_launch(void* const* d_in, const int* in_sizes, int n_in,
                              void* d_out, int out_size)
{
    const float4* f     = (const float4*)d_in[0];
    const float4* g     = (const float4*)d_in[1];
    const int*    f_len = (const int*)d_in[2];
    const int*    g_len = (const int*)d_in[3];
    float*        out   = (float*)d_out;

    dim3 grid(U_ / U_PER_BLK, T_, B_);   // (12, 256, 16)
    dim3 block(128);
    transducer_joint_kernel<<<grid, block>>>(f, g, f_len, g_len, out);
}

// round 4
// speedup vs baseline: 1.0343x; 1.0343x over previous
#include <cuda_runtime.h>

// TransducerJoint: h[b,t,u,:] = f[b,t,:] + g[b,u,:] if t < f_len[b] && u < g_len[b] else 0
// B=16, T=256, U=96, H=512 (fp32). Output 805 MB -> pure HBM-write-bound.
// R4: revert to 128-bit __stcs stores (R2 structure). U_PER_BLK=12 (24KB/block),
//     mask hoisted out of loop: valid-prefix loop then zero-fill loop.

#define B_ 16
#define T_ 256
#define U_ 96
#define H_ 512
#define H4_ (H_ / 4)      // 128 float4 per H-row
#define U_PER_BLK 12

__global__ __launch_bounds__(H4_) void transducer_joint_kernel(
    const float4* __restrict__ f,      // (B, T, H/4)
    const float4* __restrict__ g,      // (B, U, H/4)
    const int*    __restrict__ f_len,  // (B,)
    const int*    __restrict__ g_len,  // (B,)
    float4*       __restrict__ out)    // (B, T, U, H/4)
{
    const int h4 = threadIdx.x;        // 0..127
    const int u0 = blockIdx.x * U_PER_BLK;
    const int t  = blockIdx.y;
    const int b  = blockIdx.z;

    // number of valid u's in [u0, u0+U_PER_BLK) for this (b,t)
    int n_valid = 0;
    if (t < f_len[b]) {
        int r = g_len[b] - u0;
        n_valid = r < 0 ? 0 : (r > U_PER_BLK ? U_PER_BLK : r);
    }

    float4* obase = out + (((size_t)b * T_ + t) * U_ + u0) * H4_ + h4;
    const float4* gbase = g + ((size_t)b * U_ + u0) * H4_ + h4;

    if (n_valid > 0) {
        // f row chunk: loaded once, reused for all valid u's
        const float4 f4 = __ldg(f + ((size_t)b * T_ + t) * H4_ + h4);
        for (int du = 0; du < n_valid; ++du) {
            float4 g4 = __ldg(gbase + (size_t)du * H4_);
            float4 r;
            r.x = f4.x + g4.x;
            r.y = f4.y + g4.y;
            r.z = f4.z + g4.z;
            r.w = f4.w + g4.w;
            __stcs(obase + (size_t)du * H4_, r);
        }
    }

    const float4 zero = make_float4(0.f, 0.f, 0.f, 0.f);
#pragma unroll 4
    for (int du = n_valid; du < U_PER_BLK; ++du) {
        __stcs(obase + (size_t)du * H4_, zero);
    }
}

extern "C" void kernel_launch(void* const* d_in, const int* in_sizes, int n_in,
                              void* d_out, int out_size)
{
    const float4* f     = (const float4*)d_in[0];
    const float4* g     = (const float4*)d_in[1];
    const int*    f_len = (const int*)d_in[2];
    const int*    g_len = (const int*)d_in[3];
    float4*       out   = (float4*)d_out;

    dim3 grid(U_ / U_PER_BLK, T_, B_);   // (8, 256, 16)
    dim3 block(H4_);                      // 128 threads
    transducer_joint_kernel<<<grid, block>>>(f, g, f_len, g_len, out);
}

// round 5
// speedup vs baseline: 1.0464x; 1.0118x over previous
#include <cuda_runtime.h>

// TransducerJoint: h[b,t,u,:] = f[b,t,:] + g[b,u,:] if t < f_len[b] && u < g_len[b] else 0
// B=16, T=256, U=96, H=512 (fp32). Output 805 MB -> pure HBM-write-bound.
// R5: R2 (fully-unrolled predicated body, float4 __stcs) merged with R4
//     (hoisted n_valid mask, U_PER_BLK=12 -> 24KB contiguous per block).

#define B_ 16
#define T_ 256
#define U_ 96
#define H_ 512
#define H4_ (H_ / 4)      // 128 float4 per H-row
#define U_PER_BLK 12

__global__ __launch_bounds__(H4_) void transducer_joint_kernel(
    const float4* __restrict__ f,      // (B, T, H/4)
    const float4* __restrict__ g,      // (B, U, H/4)
    const int*    __restrict__ f_len,  // (B,)
    const int*    __restrict__ g_len,  // (B,)
    float4*       __restrict__ out)    // (B, T, U, H/4)
{
    const int h4 = threadIdx.x;        // 0..127
    const int u0 = blockIdx.x * U_PER_BLK;
    const int t  = blockIdx.y;
    const int b  = blockIdx.z;

    // number of valid u's in [u0, u0+U_PER_BLK) for this (b,t), computed once
    int n_valid = 0;
    if (t < f_len[b]) {
        int r = g_len[b] - u0;
        n_valid = r < 0 ? 0 : (r > U_PER_BLK ? U_PER_BLK : r);
    }

    // f row chunk: loaded once, reused for all u's
    const float4 f4 = __ldg(f + ((size_t)b * T_ + t) * H4_ + h4);

    const float4* gbase = g + ((size_t)b * U_ + u0) * H4_ + h4;
    float4* obase = out + (((size_t)b * T_ + t) * U_ + u0) * H4_ + h4;

    const float4 zero = make_float4(0.f, 0.f, 0.f, 0.f);

#pragma unroll
    for (int du = 0; du < U_PER_BLK; ++du) {
        float4 r = zero;
        if (du < n_valid) {                       // single cheap predicate
            const float4 g4 = __ldg(gbase + (size_t)du * H4_);
            r.x = f4.x + g4.x;
            r.y = f4.y + g4.y;
            r.z = f4.z + g4.z;
            r.w = f4.w + g4.w;
        }
        __stcs(obase + (size_t)du * H4_, r);      // unconditional streaming store
    }
}

extern "C" void kernel_launch(void* const* d_in, const int* in_sizes, int n_in,
                              void* d_out, int out_size)
{
    const float4* f     = (const float4*)d_in[0];
    const float4* g     = (const float4*)d_in[1];
    const int*    f_len = (const int*)d_in[2];
    const int*    g_len = (const int*)d_in[3];
    float4*       out   = (float4*)d_out;

    dim3 grid(U_ / U_PER_BLK, T_, B_);   // (8, 256, 16)
    dim3 block(H4_);                      // 128 threads
    transducer_joint_kernel<<<grid, block>>>(f, g, f_len, g_len, out);
}